// round 4
// baseline (speedup 1.0000x reference)
#include <cuda_runtime.h>
#include <cuda_bf16.h>
#include <math.h>

#define NROWS 4096        // B*T
#define TT    2048
#define CC    1024
#define HH    16
#define DD    64
#define BUF   (NROWS * CC)   // 4,194,304 floats per buffer

// 15 big buffers + t1 (4096*128)
__device__ float g_scratch[15 * BUF + NROWS * 128];

// ---------------------------------------------------------------------------
// Kernel 1: time-shift lerp -> xr, xw, xk, xv, xa
// ---------------------------------------------------------------------------
__global__ void shift_kernel(const float* __restrict__ h,
                             const float* __restrict__ cr, const float* __restrict__ cw,
                             const float* __restrict__ ck, const float* __restrict__ cv,
                             const float* __restrict__ ca,
                             float* __restrict__ oxr, float* __restrict__ oxw,
                             float* __restrict__ oxk, float* __restrict__ oxv,
                             float* __restrict__ oxa)
{
    int idx = blockIdx.x * blockDim.x + threadIdx.x;
    if (idx >= NROWS * CC) return;
    int c  = idx & (CC - 1);
    int bt = idx >> 10;
    int t  = bt & (TT - 1);
    float hv = h[idx];
    float sh = (t == 0) ? 0.f : h[idx - CC];
    float d  = sh - hv;
    oxr[idx] = hv + d * cr[c];
    oxw[idx] = hv + d * cw[c];
    oxk[idx] = hv + d * ck[c];
    oxv[idx] = hv + d * cv[c];
    oxa[idx] = hv + d * ca[c];
}

// ---------------------------------------------------------------------------
// Generic tiled SGEMM: C[M,N] = A[M,K] @ B[K,N], optional epilogue
// op: 0=none 1=tanh 2=sigmoid(y+bias) 3=logw(y+bias) 4=y+bias 5=sigmoid(y)
// BM=BN=128, BK=8, TM=TN=8, 256 threads. M always %128==0, K always %8==0.
// ---------------------------------------------------------------------------
__global__ __launch_bounds__(256)
void sgemm_k(int M, int N, int K,
             const float* __restrict__ A, const float* __restrict__ B,
             float* __restrict__ C, int op, const float* __restrict__ bias)
{
    __shared__ float As[8][128];
    __shared__ float Bs[8][128];

    const int tid  = threadIdx.x;
    const int crow = blockIdx.y;     // M tile
    const int ccol = blockIdx.x;     // N tile

    const int trow = tid >> 4;       // 0..15
    const int tcol = tid & 15;       // 0..15

    const int arow  = tid >> 1;            // 0..127
    const int acol  = (tid & 1) * 4;       // 0 or 4
    const int brow  = tid >> 5;            // 0..7
    const int bcol  = (tid & 31) * 4;      // 0..124

    const float* Ab = A + (size_t)(crow * 128) * K;

    float acc[8][8];
#pragma unroll
    for (int m = 0; m < 8; m++)
#pragma unroll
        for (int n = 0; n < 8; n++) acc[m][n] = 0.f;

    for (int k0 = 0; k0 < K; k0 += 8) {
        // load A tile (transposed into As[k][m])
        float4 av = *(const float4*)(Ab + (size_t)arow * K + k0 + acol);
        As[acol + 0][arow] = av.x;
        As[acol + 1][arow] = av.y;
        As[acol + 2][arow] = av.z;
        As[acol + 3][arow] = av.w;
        // load B tile with N guard
        int gcol = ccol * 128 + bcol;
        float bv0, bv1, bv2, bv3;
        if (gcol + 3 < N) {
            float4 bv = *(const float4*)(B + (size_t)(k0 + brow) * N + gcol);
            bv0 = bv.x; bv1 = bv.y; bv2 = bv.z; bv3 = bv.w;
        } else {
            bv0 = (gcol + 0 < N) ? B[(size_t)(k0 + brow) * N + gcol + 0] : 0.f;
            bv1 = (gcol + 1 < N) ? B[(size_t)(k0 + brow) * N + gcol + 1] : 0.f;
            bv2 = (gcol + 2 < N) ? B[(size_t)(k0 + brow) * N + gcol + 2] : 0.f;
            bv3 = (gcol + 3 < N) ? B[(size_t)(k0 + brow) * N + gcol + 3] : 0.f;
        }
        Bs[brow][bcol + 0] = bv0;
        Bs[brow][bcol + 1] = bv1;
        Bs[brow][bcol + 2] = bv2;
        Bs[brow][bcol + 3] = bv3;
        __syncthreads();

#pragma unroll
        for (int kk = 0; kk < 8; kk++) {
            float ra[8], rb[8];
#pragma unroll
            for (int m = 0; m < 8; m++) ra[m] = As[kk][trow * 8 + m];
#pragma unroll
            for (int n = 0; n < 8; n++) rb[n] = Bs[kk][tcol * 8 + n];
#pragma unroll
            for (int m = 0; m < 8; m++)
#pragma unroll
                for (int n = 0; n < 8; n++) acc[m][n] = fmaf(ra[m], rb[n], acc[m][n]);
        }
        __syncthreads();
    }

#pragma unroll
    for (int m = 0; m < 8; m++) {
        int row = crow * 128 + trow * 8 + m;
#pragma unroll
        for (int n = 0; n < 8; n++) {
            int col = ccol * 128 + tcol * 8 + n;
            if (col < N) {
                float y = acc[m][n];
                if (op == 1)      y = tanhf(y);
                else if (op == 2) { y += bias[col]; y = 1.f / (1.f + __expf(-y)); }
                else if (op == 3) {
                    y += bias[col];
                    float z  = -y;
                    float sp = fmaxf(z, 0.f) + log1pf(__expf(-fabsf(z)));
                    y = -sp - 0.5f;
                }
                else if (op == 4) y += bias[col];
                else if (op == 5) y = 1.f / (1.f + __expf(-y));
                C[(size_t)row * N + col] = y;
            }
        }
    }
}

// ---------------------------------------------------------------------------
// Per-64-segment sum inside a 1024-thread block (replicated to all threads)
// ---------------------------------------------------------------------------
__device__ __forceinline__ float seg64(float x, float* wsum, int tid)
{
#pragma unroll
    for (int o = 16; o > 0; o >>= 1) x += __shfl_xor_sync(0xffffffffu, x, o);
    __syncthreads();                       // protect wsum from prior use
    if ((tid & 31) == 0) wsum[tid >> 5] = x;
    __syncthreads();
    int w2 = (tid >> 6) << 1;
    return wsum[w2] + wsum[w2 + 1];
}

// ---------------------------------------------------------------------------
// Kernel 3: scan prep. kk = normalize(k*k_k) per head; aa=-kk; bb=kk*a;
// k <- k*(1+(a-1)*k_a). One block per (b,t), 1024 threads.
// ---------------------------------------------------------------------------
__global__ void prep_kernel(float* __restrict__ k, const float* __restrict__ a,
                            const float* __restrict__ kkw, const float* __restrict__ kaw,
                            float* __restrict__ aa, float* __restrict__ bb)
{
    __shared__ float wsum[32];
    int row = blockIdx.x;
    int c   = threadIdx.x;
    size_t base = (size_t)row * CC;
    float k0  = k[base + c];
    float kkv = k0 * kkw[c];
    float ss  = seg64(kkv * kkv, wsum, c);
    float nrm = kkv / fmaxf(sqrtf(ss), 1e-12f);
    float av  = a[base + c];
    aa[base + c] = -nrm;
    bb[base + c] = nrm * av;
    k[base + c]  = k0 * (1.f + (av - 1.f) * kaw[c]);
}

// ---------------------------------------------------------------------------
// Kernel 4: sequential RWKV7 scan. One block per (b,h); 256 threads.
// thread = (i = tid>>2, q = tid&3); each owns S[i][16q..16q+15].
// One-step register prefetch hides global-load latency behind compute.
// ---------------------------------------------------------------------------
__global__ __launch_bounds__(256)
void scan_kernel(const float* __restrict__ r, const float* __restrict__ w,
                 const float* __restrict__ k, const float* __restrict__ v,
                 const float* __restrict__ aa, const float* __restrict__ bbp,
                 float* __restrict__ o)
{
    int bh = blockIdx.x;
    int b  = bh >> 4;
    int h  = bh & 15;
    int tid = threadIdx.x;
    int i = tid >> 2;
    int q = tid & 3;
    int j0 = q * 16;

    __shared__ float sr[64], swe[64], sk[64], sv[64], saa[64], sbb[64];

    float S[16];
#pragma unroll
    for (int jj = 0; jj < 16; jj++) S[jj] = 0.f;

    size_t base = (size_t)b * TT * CC + h * 64;
    int grp = tid >> 6, l = tid & 63;

    // register prefetch for current timestep
    float p0 = 0.f, p1 = 0.f;
    {
        size_t bp = base;
        if (grp == 0)      { p0 = r[bp + l];  p1 = w[bp + l]; }
        else if (grp == 1) { p0 = k[bp + l]; }
        else if (grp == 2) { p0 = aa[bp + l]; p1 = v[bp + l]; }
        else               { p0 = bbp[bp + l]; }
    }

    for (int t = 0; t < TT; t++, base += CC) {
        // publish prefetched values for step t
        if (grp == 0)      { sr[l] = p0; swe[l] = __expf(p1); }
        else if (grp == 1) { sk[l] = p0; }
        else if (grp == 2) { saa[l] = p0; sv[l] = p1; }
        else               { sbb[l] = p0; }
        __syncthreads();

        // issue loads for step t+1 (latency overlapped with compute below)
        if (t + 1 < TT) {
            size_t bp = base + CC;
            if (grp == 0)      { p0 = r[bp + l];  p1 = w[bp + l]; }
            else if (grp == 1) { p0 = k[bp + l]; }
            else if (grp == 2) { p0 = aa[bp + l]; p1 = v[bp + l]; }
            else               { p0 = bbp[bp + l]; }
        }

        float sa = 0.f;
#pragma unroll
        for (int jj = 0; jj < 16; jj++) sa = fmaf(S[jj], saa[j0 + jj], sa);
        sa += __shfl_xor_sync(0xffffffffu, sa, 1);
        sa += __shfl_xor_sync(0xffffffffu, sa, 2);

        float vi = sv[i];
        float op = 0.f;
#pragma unroll
        for (int jj = 0; jj < 16; jj++) {
            int j = j0 + jj;
            float s = fmaf(S[jj], swe[j], fmaf(sa, sbb[j], vi * sk[j]));
            S[jj] = s;
            op = fmaf(s, sr[j], op);
        }
        op += __shfl_xor_sync(0xffffffffu, op, 1);
        op += __shfl_xor_sync(0xffffffffu, op, 2);
        if (q == 0) o[base + i] = op;
        __syncthreads();
    }
}

// ---------------------------------------------------------------------------
// Kernel 5: GroupNorm(H groups) + bonus + gate. Block per (b,t), 1024 threads.
// ---------------------------------------------------------------------------
__global__ void post_kernel(const float* __restrict__ o, const float* __restrict__ r,
                            const float* __restrict__ k, const float* __restrict__ v,
                            const float* __restrict__ g, const float* __restrict__ rk,
                            const float* __restrict__ gnw, const float* __restrict__ gnb,
                            float* __restrict__ out)
{
    __shared__ float wsum[32];
    int row = blockIdx.x;
    int c   = threadIdx.x;
    size_t base = (size_t)row * CC;

    float ov = o[base + c];
    float mu = seg64(ov, wsum, c) * (1.f / 64.f);
    float dv = ov - mu;
    float var = seg64(dv * dv, wsum, c) * (1.f / 64.f);
    float rv = r[base + c], kv = k[base + c];
    float bsum = seg64(rv * kv * rk[c], wsum, c);
    float y = dv * rsqrtf(var + 1e-5f) * gnw[c] + gnb[c] + bsum * v[base + c];
    out[base + c] = y * g[base + c];
}

// ---------------------------------------------------------------------------
// Host launcher
// ---------------------------------------------------------------------------
extern "C" void kernel_launch(void* const* d_in, const int* in_sizes, int n_in,
                              void* d_out, int out_size)
{
    const float* hs     = (const float*)d_in[0];
    const float* x_r    = (const float*)d_in[1];
    const float* x_w    = (const float*)d_in[2];
    const float* x_k    = (const float*)d_in[3];
    const float* x_v    = (const float*)d_in[4];
    const float* x_a    = (const float*)d_in[5];
    // d_in[6] = x_g (unused by reference)
    const float* k_k    = (const float*)d_in[7];
    const float* k_a    = (const float*)d_in[8];
    const float* r_k    = (const float*)d_in[9];
    const float* W_r    = (const float*)d_in[10];
    const float* W_k    = (const float*)d_in[11];
    const float* W_v    = (const float*)d_in[12];
    const float* W_o    = (const float*)d_in[13];
    const float* wla    = (const float*)d_in[14];
    const float* wlb    = (const float*)d_in[15];
    const float* wlbias = (const float*)d_in[16];
    const float* ala    = (const float*)d_in[17];
    const float* alb    = (const float*)d_in[18];
    const float* albias = (const float*)d_in[19];
    const float* gla    = (const float*)d_in[20];
    const float* glb    = (const float*)d_in[21];
    const float* glbias = (const float*)d_in[22];
    const float* gnw    = (const float*)d_in[23];
    const float* gnb    = (const float*)d_in[24];

    void* sp = nullptr;
    cudaGetSymbolAddress(&sp, g_scratch);
    float* S = (float*)sp;
    float* xr    = S + 0  * BUF;
    float* xw    = S + 1  * BUF;
    float* xk    = S + 2  * BUF;
    float* xv    = S + 3  * BUF;
    float* xa    = S + 4  * BUF;
    float* rb    = S + 5  * BUF;
    float* kb    = S + 6  * BUF;
    float* vb    = S + 7  * BUF;
    float* wb    = S + 8  * BUF;
    float* ab    = S + 9  * BUF;
    float* gb    = S + 10 * BUF;
    float* aaB   = S + 11 * BUF;
    float* bbB   = S + 12 * BUF;
    float* oB    = S + 13 * BUF;
    float* gated = S + 14 * BUF;
    float* t1    = S + 15 * BUF;

    shift_kernel<<<(NROWS * CC + 255) / 256, 256>>>(hs, x_r, x_w, x_k, x_v, x_a,
                                                    xr, xw, xk, xv, xa);

    auto gemm = [&](const float* A, const float* B, float* Cm, int N, int K,
                    int op, const float* bias) {
        dim3 grid((N + 127) / 128, NROWS / 128);
        sgemm_k<<<grid, 256>>>(NROWS, N, K, A, B, Cm, op, bias);
    };

    // square projections
    gemm(xr, W_r, rb, CC, CC, 0, nullptr);
    gemm(xk, W_k, kb, CC, CC, 0, nullptr);
    gemm(xv, W_v, vb, CC, CC, 0, nullptr);

    // w LoRA: logw = -softplus(-(tanh(xw@A)@B + bias)) - 0.5
    gemm(xw, wla, t1, 64, CC, 1, nullptr);
    gemm(t1, wlb, wb, CC, 64, 3, wlbias);

    // a LoRA: a = sigmoid((xa@A)@B + bias)
    gemm(xa, ala, t1, 64, CC, 0, nullptr);
    gemm(t1, alb, ab, CC, 64, 2, albias);

    // g LoRA: g = sigmoid(r@A)@B + bias
    gemm(rb, gla, t1, 128, CC, 5, nullptr);
    gemm(t1, glb, gb, CC, 128, 4, glbias);

    prep_kernel<<<NROWS, 1024>>>(kb, ab, k_k, k_a, aaB, bbB);

    scan_kernel<<<32, 256>>>(rb, wb, kb, vb, aaB, bbB, oB);

    post_kernel<<<NROWS, 1024>>>(oB, rb, kb, vb, gb, r_k, gnw, gnb, gated);

    gemm(gated, W_o, (float*)d_out, CC, CC, 0, nullptr);
}

// round 11
// speedup vs baseline: 1.4840x; 1.4840x over previous
#include <cuda_runtime.h>
#include <cuda_bf16.h>
#include <math.h>
#include <stdint.h>

#define NROWS 4096        // B*T
#define TT    2048
#define CC    1024
#define HH    16
#define DD    64
#define BUF   (NROWS * CC)   // 4,194,304 floats

// ---------------------------------------------------------------------------
// Scratch layout (floats)
// ---------------------------------------------------------------------------
#define OF_XR     ((size_t)0)
#define OF_XW     (OF_XR + BUF)
#define OF_XK     (OF_XW + BUF)
#define OF_XV     (OF_XK + BUF)
#define OF_XA     (OF_XV + BUF)
#define OF_RB     (OF_XA + BUF)
#define OF_KB     (OF_RB + BUF)
#define OF_VB     (OF_KB + BUF)
#define OF_WB     (OF_VB + BUF)
#define OF_AB     (OF_WB + BUF)
#define OF_GB     (OF_AB + BUF)
#define OF_OB     (OF_GB + BUF)
#define OF_GATED  (OF_OB + BUF)
#define OF_T1     (OF_GATED + BUF)
#define OF_PACK   (OF_T1 + (size_t)NROWS * 128)
#define PACK_SZ   ((size_t)32 * 2048 * 384)
#define OF_AH     (OF_PACK + PACK_SZ)          // bf16 4096x1024 -> BUF/2 floats
#define OF_AL     (OF_AH + BUF / 2)
#define OF_WT     (OF_AL + BUF / 2)            // 8 x (1024x1024 bf16 = 524288 floats)
#define WT_SZ     ((size_t)524288)
#define OF_LWT    (OF_WT + 8 * WT_SZ)          // 6 x (128x1024 bf16 = 65536 floats)
#define LWT_SZ    ((size_t)65536)
#define TOTAL_FL  (OF_LWT + 6 * LWT_SZ)

__device__ float g_scratch[TOTAL_FL];

// ---------------------------------------------------------------------------
// mma.sync m16n8k16 bf16 (baseline PTX, compiles for plain sm_103)
// ---------------------------------------------------------------------------
__device__ __forceinline__ void mma16816(float* d, uint32_t a0, uint32_t a1,
                                         uint32_t a2, uint32_t a3,
                                         uint32_t b0, uint32_t b1)
{
    asm volatile(
        "mma.sync.aligned.m16n8k16.row.col.f32.bf16.bf16.f32 "
        "{%0,%1,%2,%3},{%4,%5,%6,%7},{%8,%9},{%0,%1,%2,%3};"
        : "+f"(d[0]), "+f"(d[1]), "+f"(d[2]), "+f"(d[3])
        : "r"(a0), "r"(a1), "r"(a2), "r"(a3), "r"(b0), "r"(b1));
}

// ---------------------------------------------------------------------------
// Split-bf16 HMMA GEMM: C[4096, Nreal] = A[4096,1024] @ Wt^T
// A as Ah+Al bf16 (lda=1024), Wt as hi/lo [128*gridx rows][1024] bf16 (padded).
// Block tile 128x128, 8 warps (2m x 4n), warp tile 64x32, k-step 16.
// op: 0 none, 1 tanh, 5 sigmoid. Stores guarded to col < Nreal, row stride ldc.
// ---------------------------------------------------------------------------
__global__ __launch_bounds__(256, 2)
void hgemm_split(const __nv_bfloat16* __restrict__ Ah, const __nv_bfloat16* __restrict__ Al,
                 const __nv_bfloat16* __restrict__ Bh, const __nv_bfloat16* __restrict__ Bl,
                 float* __restrict__ C, int ldc, int Nreal, int op)
{
    __shared__ __nv_bfloat16 sAh[128 * 16], sAl[128 * 16];
    __shared__ __nv_bfloat16 sBh[128 * 16], sBl[128 * 16];

    const int tid  = threadIdx.x;
    const int lane = tid & 31;
    const int wid  = tid >> 5;
    const int wm   = (wid & 1) * 64;
    const int wn   = (wid >> 1) * 32;
    const int mbase = blockIdx.y * 128;
    const int nbase = blockIdx.x * 128;

    const int lrow  = tid >> 1;          // 0..127
    const int lhalf = (tid & 1) * 8;     // 0 or 8 (bf16 elems)

    const __nv_bfloat16* gAh = Ah + (size_t)(mbase + lrow) * 1024 + lhalf;
    const __nv_bfloat16* gAl = Al + (size_t)(mbase + lrow) * 1024 + lhalf;
    const __nv_bfloat16* gBh = Bh + (size_t)(nbase + lrow) * 1024 + lhalf;
    const __nv_bfloat16* gBl = Bl + (size_t)(nbase + lrow) * 1024 + lhalf;

    float acc[4][4][4];
#pragma unroll
    for (int mi = 0; mi < 4; mi++)
#pragma unroll
        for (int nj = 0; nj < 4; nj++)
#pragma unroll
            for (int e = 0; e < 4; e++) acc[mi][nj][e] = 0.f;

    const int bq  = (lane & 3) * 2;   // k-pair base
    const int nfr = lane >> 2;        // 0..7

    uint4 rAh = *(const uint4*)gAh;
    uint4 rAl = *(const uint4*)gAl;
    uint4 rBh = *(const uint4*)gBh;
    uint4 rBl = *(const uint4*)gBl;

    for (int s = 0; s < 64; s++) {
        *(uint4*)(sAh + lrow * 16 + lhalf) = rAh;
        *(uint4*)(sAl + lrow * 16 + lhalf) = rAl;
        *(uint4*)(sBh + lrow * 16 + lhalf) = rBh;
        *(uint4*)(sBl + lrow * 16 + lhalf) = rBl;
        __syncthreads();

        if (s < 63) {
            rAh = *(const uint4*)(gAh + (s + 1) * 16);
            rAl = *(const uint4*)(gAl + (s + 1) * 16);
            rBh = *(const uint4*)(gBh + (s + 1) * 16);
            rBl = *(const uint4*)(gBl + (s + 1) * 16);
        }

        // B fragments (all 4 n-frags, hi+lo)
        uint32_t fbh[4][2], fbl[4][2];
#pragma unroll
        for (int nj = 0; nj < 4; nj++) {
            int n = wn + nj * 8 + nfr;
            fbh[nj][0] = *(const uint32_t*)(sBh + n * 16 + bq);
            fbh[nj][1] = *(const uint32_t*)(sBh + n * 16 + bq + 8);
            fbl[nj][0] = *(const uint32_t*)(sBl + n * 16 + bq);
            fbl[nj][1] = *(const uint32_t*)(sBl + n * 16 + bq + 8);
        }

#pragma unroll
        for (int mi = 0; mi < 4; mi++) {
            int r = wm + mi * 16 + nfr;
            uint32_t ah0 = *(const uint32_t*)(sAh + r * 16 + bq);
            uint32_t ah1 = *(const uint32_t*)(sAh + (r + 8) * 16 + bq);
            uint32_t ah2 = *(const uint32_t*)(sAh + r * 16 + bq + 8);
            uint32_t ah3 = *(const uint32_t*)(sAh + (r + 8) * 16 + bq + 8);
            uint32_t al0 = *(const uint32_t*)(sAl + r * 16 + bq);
            uint32_t al1 = *(const uint32_t*)(sAl + (r + 8) * 16 + bq);
            uint32_t al2 = *(const uint32_t*)(sAl + r * 16 + bq + 8);
            uint32_t al3 = *(const uint32_t*)(sAl + (r + 8) * 16 + bq + 8);
#pragma unroll
            for (int nj = 0; nj < 4; nj++) {
                mma16816(acc[mi][nj], ah0, ah1, ah2, ah3, fbh[nj][0], fbh[nj][1]);
                mma16816(acc[mi][nj], ah0, ah1, ah2, ah3, fbl[nj][0], fbl[nj][1]);
                mma16816(acc[mi][nj], al0, al1, al2, al3, fbh[nj][0], fbh[nj][1]);
            }
        }
        __syncthreads();
    }

    // epilogue
#pragma unroll
    for (int mi = 0; mi < 4; mi++) {
        int r0 = mbase + wm + mi * 16 + nfr;
#pragma unroll
        for (int nj = 0; nj < 4; nj++) {
            int c = nbase + wn + nj * 8 + bq;
            if (c < Nreal) {
                float y0 = acc[mi][nj][0], y1 = acc[mi][nj][1];
                float y2 = acc[mi][nj][2], y3 = acc[mi][nj][3];
                if (op == 1) {
                    y0 = tanhf(y0); y1 = tanhf(y1); y2 = tanhf(y2); y3 = tanhf(y3);
                } else if (op == 5) {
                    y0 = 1.f / (1.f + __expf(-y0));
                    y1 = 1.f / (1.f + __expf(-y1));
                    y2 = 1.f / (1.f + __expf(-y2));
                    y3 = 1.f / (1.f + __expf(-y3));
                }
                *(float2*)(C + (size_t)r0 * ldc + c)       = make_float2(y0, y1);
                *(float2*)(C + (size_t)(r0 + 8) * ldc + c) = make_float2(y2, y3);
            }
        }
    }
}

// ---------------------------------------------------------------------------
// fp32 -> bf16 hi/lo split
// ---------------------------------------------------------------------------
__global__ void split_kernel(const float* __restrict__ X, __nv_bfloat16* __restrict__ H,
                             __nv_bfloat16* __restrict__ L, int n2)
{
    int idx = blockIdx.x * blockDim.x + threadIdx.x;
    if (idx >= n2) return;
    float2 x = ((const float2*)X)[idx];
    __nv_bfloat16 h0 = __float2bfloat16(x.x);
    __nv_bfloat16 h1 = __float2bfloat16(x.y);
    __nv_bfloat162 hh; hh.x = h0; hh.y = h1;
    __nv_bfloat162 ll;
    ll.x = __float2bfloat16(x.x - __bfloat162float(h0));
    ll.y = __float2bfloat16(x.y - __bfloat162float(h1));
    ((__nv_bfloat162*)H)[idx] = hh;
    ((__nv_bfloat162*)L)[idx] = ll;
}

// ---------------------------------------------------------------------------
// W[k=1024 rows][N cols] (row stride ldw=N) -> Wt hi/lo [n][1024] bf16
// grid (N/32, 32), block (32,8)
// ---------------------------------------------------------------------------
__global__ void transpose_split(const float* __restrict__ W, int ldw,
                                __nv_bfloat16* __restrict__ Th, __nv_bfloat16* __restrict__ Tl)
{
    __shared__ float tile[32][33];
    int bx = blockIdx.x * 32;   // n block
    int by = blockIdx.y * 32;   // k block
    int tx = threadIdx.x, ty = threadIdx.y;
#pragma unroll
    for (int i = 0; i < 32; i += 8)
        tile[ty + i][tx] = W[(size_t)(by + ty + i) * ldw + bx + tx];  // tile[k'][n']
    __syncthreads();
#pragma unroll
    for (int i = 0; i < 32; i += 8) {
        float x = tile[tx][ty + i];                 // k'=tx, n'=ty+i
        __nv_bfloat16 h = __float2bfloat16(x);
        size_t o = (size_t)(bx + ty + i) * 1024 + by + tx;
        Th[o] = h;
        Tl[o] = __float2bfloat16(x - __bfloat162float(h));
    }
}

// ---------------------------------------------------------------------------
// time-shift lerp
// ---------------------------------------------------------------------------
__global__ void shift_kernel(const float* __restrict__ h,
                             const float* __restrict__ cr, const float* __restrict__ cw,
                             const float* __restrict__ ck, const float* __restrict__ cv,
                             const float* __restrict__ ca,
                             float* __restrict__ oxr, float* __restrict__ oxw,
                             float* __restrict__ oxk, float* __restrict__ oxv,
                             float* __restrict__ oxa)
{
    int idx = blockIdx.x * blockDim.x + threadIdx.x;
    if (idx >= NROWS * CC) return;
    int c  = idx & (CC - 1);
    int bt = idx >> 10;
    int t  = bt & (TT - 1);
    float hv = h[idx];
    float sh = (t == 0) ? 0.f : h[idx - CC];
    float d  = sh - hv;
    oxr[idx] = hv + d * cr[c];
    oxw[idx] = hv + d * cw[c];
    oxk[idx] = hv + d * ck[c];
    oxv[idx] = hv + d * cv[c];
    oxa[idx] = hv + d * ca[c];
}

// ---------------------------------------------------------------------------
// FP32 SGEMM: used for the small-K LoRA-B projections
// op: 0=none 2=sigmoid(y+bias) 3=logw(y+bias) 4=y+bias
// ---------------------------------------------------------------------------
__global__ __launch_bounds__(256)
void sgemm_k(int M, int N, int K,
             const float* __restrict__ A, const float* __restrict__ B,
             float* __restrict__ C, int op, const float* __restrict__ bias)
{
    __shared__ float As[8][128];
    __shared__ float Bs[8][128];
    const int tid  = threadIdx.x;
    const int crow = blockIdx.y;
    const int ccol = blockIdx.x;
    const int trow = tid >> 4;
    const int tcol = tid & 15;
    const int arow = tid >> 1;
    const int acol = (tid & 1) * 4;
    const int brow = tid >> 5;
    const int bcol = (tid & 31) * 4;
    const float* Ab = A + (size_t)(crow * 128) * K;

    float acc[8][8];
#pragma unroll
    for (int m = 0; m < 8; m++)
#pragma unroll
        for (int n = 0; n < 8; n++) acc[m][n] = 0.f;

    for (int k0 = 0; k0 < K; k0 += 8) {
        float4 av = *(const float4*)(Ab + (size_t)arow * K + k0 + acol);
        As[acol + 0][arow] = av.x;
        As[acol + 1][arow] = av.y;
        As[acol + 2][arow] = av.z;
        As[acol + 3][arow] = av.w;
        int gcol = ccol * 128 + bcol;
        float4 bv = *(const float4*)(B + (size_t)(k0 + brow) * N + gcol);
        Bs[brow][bcol + 0] = bv.x;
        Bs[brow][bcol + 1] = bv.y;
        Bs[brow][bcol + 2] = bv.z;
        Bs[brow][bcol + 3] = bv.w;
        __syncthreads();
#pragma unroll
        for (int kk = 0; kk < 8; kk++) {
            float ra[8], rb[8];
#pragma unroll
            for (int m = 0; m < 8; m++) ra[m] = As[kk][trow * 8 + m];
#pragma unroll
            for (int n = 0; n < 8; n++) rb[n] = Bs[kk][tcol * 8 + n];
#pragma unroll
            for (int m = 0; m < 8; m++)
#pragma unroll
                for (int n = 0; n < 8; n++) acc[m][n] = fmaf(ra[m], rb[n], acc[m][n]);
        }
        __syncthreads();
    }
#pragma unroll
    for (int m = 0; m < 8; m++) {
        int row = crow * 128 + trow * 8 + m;
#pragma unroll
        for (int n = 0; n < 8; n++) {
            int col = ccol * 128 + tcol * 8 + n;
            float y = acc[m][n];
            if (op == 2)      { y += bias[col]; y = 1.f / (1.f + __expf(-y)); }
            else if (op == 3) {
                y += bias[col];
                float z  = -y;
                float sp = fmaxf(z, 0.f) + log1pf(__expf(-fabsf(z)));
                y = -sp - 0.5f;
            }
            else if (op == 4) y += bias[col];
            C[(size_t)row * N + col] = y;
        }
    }
}

// ---------------------------------------------------------------------------
// seg64 reduction (per 64-channel head inside 1024-thread block)
// ---------------------------------------------------------------------------
__device__ __forceinline__ float seg64(float x, float* wsum, int tid)
{
#pragma unroll
    for (int o = 16; o > 0; o >>= 1) x += __shfl_xor_sync(0xffffffffu, x, o);
    __syncthreads();
    if ((tid & 31) == 0) wsum[tid >> 5] = x;
    __syncthreads();
    int w2 = (tid >> 6) << 1;
    return wsum[w2] + wsum[w2 + 1];
}

// ---------------------------------------------------------------------------
// prep + pack -> [bh][t][384]: r, exp(w), k_new, v, aa, bb
// ---------------------------------------------------------------------------
__global__ void prep_pack(const float* __restrict__ r, const float* __restrict__ w,
                          float* __restrict__ k, const float* __restrict__ v,
                          const float* __restrict__ a,
                          const float* __restrict__ kkw, const float* __restrict__ kaw,
                          float* __restrict__ pk)
{
    __shared__ float wsum[32];
    int row = blockIdx.x;                 // b*2048 + t
    int c   = threadIdx.x;
    int b   = row >> 11;
    int t   = row & 2047;
    int h   = c >> 6;
    int d   = c & 63;
    size_t base = (size_t)row * CC;

    float k0  = k[base + c];
    float kkv = k0 * kkw[c];
    float ss  = seg64(kkv * kkv, wsum, c);
    float nrm = kkv / fmaxf(sqrtf(ss), 1e-12f);
    float av  = a[base + c];
    float kn  = k0 * (1.f + (av - 1.f) * kaw[c]);
    k[base + c] = kn;

    size_t pb = ((size_t)(b * 16 + h) * 2048 + t) * 384;
    pk[pb + 0 * 64 + d] = r[base + c];
    pk[pb + 1 * 64 + d] = __expf(w[base + c]);
    pk[pb + 2 * 64 + d] = kn;
    pk[pb + 3 * 64 + d] = v[base + c];
    pk[pb + 4 * 64 + d] = -nrm;
    pk[pb + 5 * 64 + d] = nrm * av;
}

// ---------------------------------------------------------------------------
// RWKV7 scan, packed input, distance-3 register prefetch. grid 32, 256 thr.
// ---------------------------------------------------------------------------
__global__ __launch_bounds__(256)
void scan_kernel(const float* __restrict__ pk, float* __restrict__ o)
{
    int bh = blockIdx.x;
    int b  = bh >> 4;
    int h  = bh & 15;
    int tid = threadIdx.x;
    int i = tid >> 2;
    int q = tid & 3;
    int j0 = q * 16;

    __shared__ float sbuf[384];
    float* sr  = sbuf;
    float* swe = sbuf + 64;
    float* sk  = sbuf + 128;
    float* sv  = sbuf + 192;
    float* saa = sbuf + 256;
    float* sbb = sbuf + 320;

    const float2* pp = (const float2*)(pk + (size_t)bh * 2048 * 384);  // 192 float2/step

    float S[16];
#pragma unroll
    for (int jj = 0; jj < 16; jj++) S[jj] = 0.f;

    float2 pA = make_float2(0.f, 0.f), pB = pA, pC = pA;
    if (tid < 192) {
        pA = pp[(size_t)0 * 192 + tid];
        pB = pp[(size_t)1 * 192 + tid];
        pC = pp[(size_t)2 * 192 + tid];
    }

    size_t obase = (size_t)b * TT * CC + h * 64;

    for (int t = 0; t < TT; t++, obase += CC) {
        if (tid < 192) ((float2*)sbuf)[tid] = pA;
        __syncthreads();

        float2 tmp = pA;
        if (tid < 192 && t + 3 < TT) tmp = pp[(size_t)(t + 3) * 192 + tid];

        float sa = 0.f;
#pragma unroll
        for (int jj = 0; jj < 16; jj++) sa = fmaf(S[jj], saa[j0 + jj], sa);
        sa += __shfl_xor_sync(0xffffffffu, sa, 1);
        sa += __shfl_xor_sync(0xffffffffu, sa, 2);

        float vi = sv[i];
        float op = 0.f;
#pragma unroll
        for (int jj = 0; jj < 16; jj++) {
            int j = j0 + jj;
            float s = fmaf(S[jj], swe[j], fmaf(sa, sbb[j], vi * sk[j]));
            S[jj] = s;
            op = fmaf(s, sr[j], op);
        }
        op += __shfl_xor_sync(0xffffffffu, op, 1);
        op += __shfl_xor_sync(0xffffffffu, op, 2);
        if (q == 0) o[obase + i] = op;
        __syncthreads();

        pA = pB; pB = pC; pC = tmp;
    }
}

// ---------------------------------------------------------------------------
// GroupNorm + bonus + gate
// ---------------------------------------------------------------------------
__global__ void post_kernel(const float* __restrict__ o, const float* __restrict__ r,
                            const float* __restrict__ k, const float* __restrict__ v,
                            const float* __restrict__ g, const float* __restrict__ rk,
                            const float* __restrict__ gnw, const float* __restrict__ gnb,
                            float* __restrict__ out)
{
    __shared__ float wsum[32];
    int row = blockIdx.x;
    int c   = threadIdx.x;
    size_t base = (size_t)row * CC;

    float ov = o[base + c];
    float mu = seg64(ov, wsum, c) * (1.f / 64.f);
    float dv = ov - mu;
    float var = seg64(dv * dv, wsum, c) * (1.f / 64.f);
    float rv = r[base + c], kv = k[base + c];
    float bsum = seg64(rv * kv * rk[c], wsum, c);
    float y = dv * rsqrtf(var + 1e-5f) * gnw[c] + gnb[c] + bsum * v[base + c];
    out[base + c] = y * g[base + c];
}

// ---------------------------------------------------------------------------
// Host launcher
// ---------------------------------------------------------------------------
extern "C" void kernel_launch(void* const* d_in, const int* in_sizes, int n_in,
                              void* d_out, int out_size)
{
    const float* hs     = (const float*)d_in[0];
    const float* x_r    = (const float*)d_in[1];
    const float* x_w    = (const float*)d_in[2];
    const float* x_k    = (const float*)d_in[3];
    const float* x_v    = (const float*)d_in[4];
    const float* x_a    = (const float*)d_in[5];
    const float* k_k    = (const float*)d_in[7];
    const float* k_a    = (const float*)d_in[8];
    const float* r_k    = (const float*)d_in[9];
    const float* W_r    = (const float*)d_in[10];
    const float* W_k    = (const float*)d_in[11];
    const float* W_v    = (const float*)d_in[12];
    const float* W_o    = (const float*)d_in[13];
    const float* wla    = (const float*)d_in[14];
    const float* wlb    = (const float*)d_in[15];
    const float* wlbias = (const float*)d_in[16];
    const float* ala    = (const float*)d_in[17];
    const float* alb    = (const float*)d_in[18];
    const float* albias = (const float*)d_in[19];
    const float* gla    = (const float*)d_in[20];
    const float* glb    = (const float*)d_in[21];
    const float* glbias = (const float*)d_in[22];
    const float* gnw    = (const float*)d_in[23];
    const float* gnb    = (const float*)d_in[24];

    void* sp = nullptr;
    cudaGetSymbolAddress(&sp, g_scratch);
    float* S = (float*)sp;
    float* xr    = S + OF_XR;
    float* xw    = S + OF_XW;
    float* xk    = S + OF_XK;
    float* xv    = S + OF_XV;
    float* xa    = S + OF_XA;
    float* rb    = S + OF_RB;
    float* kb    = S + OF_KB;
    float* vb    = S + OF_VB;
    float* wb    = S + OF_WB;
    float* ab    = S + OF_AB;
    float* gb    = S + OF_GB;
    float* oB    = S + OF_OB;
    float* gated = S + OF_GATED;
    float* t1    = S + OF_T1;
    float* packb = S + OF_PACK;
    __nv_bfloat16* ah  = (__nv_bfloat16*)(S + OF_AH);
    __nv_bfloat16* al  = (__nv_bfloat16*)(S + OF_AL);
    __nv_bfloat16* wrh = (__nv_bfloat16*)(S + OF_WT + 0 * WT_SZ);
    __nv_bfloat16* wrl = (__nv_bfloat16*)(S + OF_WT + 1 * WT_SZ);
    __nv_bfloat16* wkh = (__nv_bfloat16*)(S + OF_WT + 2 * WT_SZ);
    __nv_bfloat16* wkl = (__nv_bfloat16*)(S + OF_WT + 3 * WT_SZ);
    __nv_bfloat16* wvh = (__nv_bfloat16*)(S + OF_WT + 4 * WT_SZ);
    __nv_bfloat16* wvl = (__nv_bfloat16*)(S + OF_WT + 5 * WT_SZ);
    __nv_bfloat16* woh = (__nv_bfloat16*)(S + OF_WT + 6 * WT_SZ);
    __nv_bfloat16* wol = (__nv_bfloat16*)(S + OF_WT + 7 * WT_SZ);
    __nv_bfloat16* lwh = (__nv_bfloat16*)(S + OF_LWT + 0 * LWT_SZ);  // wla^T padded 128
    __nv_bfloat16* lwl = (__nv_bfloat16*)(S + OF_LWT + 1 * LWT_SZ);
    __nv_bfloat16* lah = (__nv_bfloat16*)(S + OF_LWT + 2 * LWT_SZ);  // ala^T
    __nv_bfloat16* lal = (__nv_bfloat16*)(S + OF_LWT + 3 * LWT_SZ);
    __nv_bfloat16* lgh = (__nv_bfloat16*)(S + OF_LWT + 4 * LWT_SZ);  // gla^T
    __nv_bfloat16* lgl = (__nv_bfloat16*)(S + OF_LWT + 5 * LWT_SZ);

    shift_kernel<<<(NROWS * CC + 255) / 256, 256>>>(hs, x_r, x_w, x_k, x_v, x_a,
                                                    xr, xw, xk, xv, xa);

    dim3 tb(32, 8);
    transpose_split<<<dim3(32, 32), tb>>>(W_r, 1024, wrh, wrl);
    transpose_split<<<dim3(32, 32), tb>>>(W_k, 1024, wkh, wkl);
    transpose_split<<<dim3(32, 32), tb>>>(W_v, 1024, wvh, wvl);
    transpose_split<<<dim3(32, 32), tb>>>(W_o, 1024, woh, wol);
    transpose_split<<<dim3(2, 32), tb>>>(wla, 64, lwh, lwl);    // rows 64..127 stay zero, guarded
    transpose_split<<<dim3(2, 32), tb>>>(ala, 64, lah, lal);
    transpose_split<<<dim3(4, 32), tb>>>(gla, 128, lgh, lgl);

    const dim3 gBig(8, 32), gLora(1, 32);
    const int SPLITB = (BUF / 2 + 255) / 256;

    auto gemm = [&](const float* A, const float* B, float* Cm, int N, int K,
                    int op, const float* bias) {
        dim3 grid(N / 128, NROWS / 128);
        sgemm_k<<<grid, 256>>>(NROWS, N, K, A, B, Cm, op, bias);
    };

    // w LoRA: tanh(xw@wla) -> t1[.,64]; then logw epilogue
    split_kernel<<<SPLITB, 256>>>(xw, ah, al, BUF / 2);
    hgemm_split<<<gLora, 256>>>(ah, al, lwh, lwl, t1, 64, 64, 1);
    gemm(t1, wlb, wb, CC, 64, 3, wlbias);

    // a LoRA: sigmoid((xa@ala)@alb + bias)
    split_kernel<<<SPLITB, 256>>>(xa, ah, al, BUF / 2);
    hgemm_split<<<gLora, 256>>>(ah, al, lah, lal, t1, 64, 64, 0);
    gemm(t1, alb, ab, CC, 64, 2, albias);

    // big projections
    split_kernel<<<SPLITB, 256>>>(xr, ah, al, BUF / 2);
    hgemm_split<<<gBig, 256>>>(ah, al, wrh, wrl, rb, 1024, 1024, 0);
    split_kernel<<<SPLITB, 256>>>(xk, ah, al, BUF / 2);
    hgemm_split<<<gBig, 256>>>(ah, al, wkh, wkl, kb, 1024, 1024, 0);
    split_kernel<<<SPLITB, 256>>>(xv, ah, al, BUF / 2);
    hgemm_split<<<gBig, 256>>>(ah, al, wvh, wvl, vb, 1024, 1024, 0);

    // g LoRA: sigmoid(rb@gla) -> t1[.,128]; then @glb + bias
    split_kernel<<<SPLITB, 256>>>(rb, ah, al, BUF / 2);
    hgemm_split<<<gLora, 256>>>(ah, al, lgh, lgl, t1, 128, 128, 5);
    gemm(t1, glb, gb, CC, 128, 4, glbias);

    prep_pack<<<NROWS, 1024>>>(rb, wb, kb, vb, ab, k_k, k_a, packb);

    scan_kernel<<<32, 256>>>(packb, oB);

    post_kernel<<<NROWS, 1024>>>(oB, rb, kb, vb, gb, r_k, gnw, gnb, gated);

    split_kernel<<<SPLITB, 256>>>(gated, ah, al, BUF / 2);
    hgemm_split<<<gBig, 256>>>(ah, al, woh, wol, (float*)d_out, 1024, 1024, 0);
}